// round 8
// baseline (speedup 1.0000x reference)
#include <cuda_runtime.h>
#include <math.h>
#include <cstdint>

#define B_  4
#define S_  2048
#define D_  768
#define H_  12
#define HD_ 64
#define SHD (S_ * HD_)          // 131072 floats per (b,h)

// Device-global scratch (cudaMalloc forbidden).
// g_Q: A-fragment packed  [bh][mt(128)][kk(8)][lane(32)][4]      (pre-scaled log2e/8)
// g_K: B-frag pair-packed [bh][nt(256)][kkp(4)][lane(32)][4]     (GEMM1 B, kk pairs)
// g_V: B-frag pair-packed [bh][kt(256)][ndp(4)][lane(32)][4]     (GEMM2 B, nd pairs)
__device__ float g_Q[B_ * H_ * SHD];
__device__ float g_K[B_ * H_ * SHD];
__device__ float g_V[B_ * H_ * SHD];
__device__ float g_Xr[B_ * S_ * D_];   // tf32-rounded X
__device__ float g_Wr[3 * D_ * D_];    // tf32-rounded Wq|Wk|Wv

// ---------------------------------------------------------------------------
__device__ __forceinline__ float tf32r(float x) {
    uint32_t u;
    asm("cvt.rna.tf32.f32 %0, %1;" : "=r"(u) : "f"(x));
    return __uint_as_float(u);
}
__device__ __forceinline__ float ex2f(float x) {
    float y;
    asm("ex2.approx.f32 %0, %1;" : "=f"(y) : "f"(x));
    return y;
}
__device__ __forceinline__ void mma8(float* d, const float* a, float b0, float b1) {
    asm volatile(
        "mma.sync.aligned.m16n8k8.row.col.f32.tf32.tf32.f32 "
        "{%0,%1,%2,%3}, {%4,%5,%6,%7}, {%8,%9}, {%0,%1,%2,%3};"
        : "+f"(d[0]), "+f"(d[1]), "+f"(d[2]), "+f"(d[3])
        : "r"(__float_as_uint(a[0])), "r"(__float_as_uint(a[1])),
          "r"(__float_as_uint(a[2])), "r"(__float_as_uint(a[3])),
          "r"(__float_as_uint(b0)), "r"(__float_as_uint(b1)));
}
__device__ __forceinline__ uint32_t smem_u32(const void* p) {
    uint32_t a;
    asm("{ .reg .u64 t; cvta.to.shared.u64 t, %1; cvt.u32.u64 %0, t; }" : "=r"(a) : "l"(p));
    return a;
}
#define CP16(dst, src) \
    asm volatile("cp.async.cg.shared.global [%0], [%1], 16;" :: "r"(dst), "l"(src) : "memory")
#define CPCOMMIT() asm volatile("cp.async.commit_group;" ::: "memory")

// fragment-pack offset helpers (writer side); tok in [0,2048), d in [0,64)
__device__ __forceinline__ int q_off(int tok, int d) {
    int mt = tok >> 4, qr = tok & 7, half = (tok >> 3) & 1;
    int kk = d >> 3, qc = d & 3, colh = (d >> 2) & 1;
    return mt * 1024 + kk * 128 + (qr * 4 + qc) * 4 + half + 2 * colh;
}
__device__ __forceinline__ int k_off(int tok, int d) {
    int nt = tok >> 3, qr = tok & 7;
    int kk = d >> 3, qc = d & 3, sl = (d >> 2) & 1;
    int kkp = kk >> 1, par = kk & 1;
    return nt * 512 + kkp * 128 + (qr * 4 + qc) * 4 + par * 2 + sl;
}
__device__ __forceinline__ int v_off(int tok, int d) {
    int kt = tok >> 3, qcv = tok & 3, sl = (tok >> 2) & 1;
    int nd = d >> 3, qrv = d & 7;
    int ndp = nd >> 1, par = nd & 1;
    return kt * 512 + ndp * 128 + (qrv * 4 + qcv) * 4 + par * 2 + sl;
}

// ---------------------------------------------------------------------------
// Kernel 0: round X and W to tf32 once.
// ---------------------------------------------------------------------------
#define NX4 ((B_ * S_ * D_) / 4)   // 1572864
#define NW4 ((D_ * D_) / 4)        // 147456

__global__ __launch_bounds__(256) void prep_round(
    const float* __restrict__ X, const float* __restrict__ Wq,
    const float* __restrict__ Wk, const float* __restrict__ Wv)
{
    int i = blockIdx.x * 256 + threadIdx.x;
    if (i < NX4) {
        float4 v = ((const float4*)X)[i];
        v.x = tf32r(v.x); v.y = tf32r(v.y); v.z = tf32r(v.z); v.w = tf32r(v.w);
        ((float4*)g_Xr)[i] = v;
    } else {
        int j = i - NX4;
        int z = j / NW4, r = j - z * NW4;
        const float4* src = (const float4*)((z == 0) ? Wq : (z == 1) ? Wk : Wv);
        float4 v = src[r];
        v.x = tf32r(v.x); v.y = tf32r(v.y); v.z = tf32r(v.z); v.w = tf32r(v.w);
        ((float4*)g_Wr)[j] = v;
    }
}

// ---------------------------------------------------------------------------
// Kernel 1: QKV projection, tf32 mma.sync + cp.async 3-stage pipeline.
// Epilogue writes fragment-packed Q/K/V (pair-packed K/V, Q pre-scaled).
// ---------------------------------------------------------------------------
#define QK_XP 36
#define QK_WP 136
#define QK_STG (128 * QK_XP + 32 * QK_WP)   // 8960 floats/stage
#define QK_SMEM (3 * QK_STG * 4)            // 107520 B

__global__ __launch_bounds__(256) void qkv_mma(
    const float* __restrict__ bq, const float* __restrict__ bk,
    const float* __restrict__ bv)
{
    extern __shared__ float smx[];

    const int tid  = threadIdx.x;
    const int lane = tid & 31;
    const int warp = tid >> 5;
    const int qr   = lane >> 2;
    const int qc   = lane & 3;
    const int wm   = warp >> 2;
    const int wn   = warp & 3;

    const int row0 = blockIdx.y * 128;
    const int col0 = blockIdx.x * 128;
    const int z    = blockIdx.z;

    const float* Wsrc = g_Wr + (size_t)z * D_ * D_;
    const float* bias = (z == 0) ? bq : (z == 1) ? bk : bv;
    float* out        = (z == 0) ? g_Q : (z == 1) ? g_K : g_V;

    const uint32_t smb = smem_u32(smx);

    auto issue = [&](int it, int s) {
        const int k0 = it * 32;
        uint32_t xb = smb + (uint32_t)(s * QK_STG) * 4;
        uint32_t wb = xb + 128 * QK_XP * 4;
#pragma unroll
        for (int i = 0; i < 4; ++i) {
            int idx = tid + i * 256;
            int r = idx >> 3, c4 = idx & 7;
            CP16(xb + (uint32_t)(r * QK_XP + c4 * 4) * 4,
                 g_Xr + (size_t)(row0 + r) * D_ + k0 + c4 * 4);
        }
#pragma unroll
        for (int i = 0; i < 4; ++i) {
            int idx = tid + i * 256;
            int r = idx >> 5, c4 = idx & 31;
            CP16(wb + (uint32_t)(r * QK_WP + c4 * 4) * 4,
                 Wsrc + (size_t)(k0 + r) * D_ + col0 + c4 * 4);
        }
    };

    float acc[4][4][4];
#pragma unroll
    for (int m = 0; m < 4; ++m)
#pragma unroll
        for (int n = 0; n < 4; ++n)
#pragma unroll
            for (int e = 0; e < 4; ++e) acc[m][n][e] = 0.0f;

    issue(0, 0); CPCOMMIT();
    issue(1, 1); CPCOMMIT();

    for (int it = 0; it < 24; ++it) {
        asm volatile("cp.async.wait_group 1;" ::: "memory");
        __syncthreads();
        if (it + 2 < 24) issue(it + 2, (it + 2) % 3);
        CPCOMMIT();

        const float* Xs = smx + (it % 3) * QK_STG;
        const float* Ws = Xs + 128 * QK_XP;

#pragma unroll
        for (int kk = 0; kk < 4; ++kk) {
            float a[4][4];
#pragma unroll
            for (int mt = 0; mt < 4; ++mt) {
                const float* p = Xs + (wm * 64 + mt * 16 + qr) * QK_XP + kk * 8 + qc;
                a[mt][0] = p[0];
                a[mt][1] = p[8 * QK_XP];
                a[mt][2] = p[4];
                a[mt][3] = p[8 * QK_XP + 4];
            }
#pragma unroll
            for (int nt = 0; nt < 4; ++nt) {
                const float* p = Ws + (kk * 8 + qc) * QK_WP + wn * 32 + nt * 8 + qr;
                float b0 = p[0];
                float b1 = p[4 * QK_WP];
#pragma unroll
                for (int mt = 0; mt < 4; ++mt) mma8(acc[mt][nt], a[mt], b0, b1);
            }
        }
    }

    // Epilogue: bias (+log2e/8 scale for Q), tf32 round, fragment-packed scatter.
    const float QSCALE = 0.18033688f;   // log2(e) / 8
#pragma unroll
    for (int mt = 0; mt < 4; ++mt) {
        int r0 = row0 + wm * 64 + mt * 16 + qr;
#pragma unroll
        for (int nt = 0; nt < 4; ++nt) {
            int gc = col0 + wn * 32 + nt * 8 + 2 * qc;
            int hh = gc >> 6, d0 = gc & 63;
            float bv0 = bias[gc], bv1 = bias[gc + 1];
            float e0[2] = { acc[mt][nt][0] + bv0, acc[mt][nt][2] + bv0 };
            float e1[2] = { acc[mt][nt][1] + bv1, acc[mt][nt][3] + bv1 };
#pragma unroll
            for (int rr = 0; rr < 2; ++rr) {
                int r = r0 + rr * 8;
                int bb = r >> 11, tok = r & (S_ - 1);
                float* base = out + ((size_t)bb * H_ + hh) * SHD;
                if (z == 0) {
                    base[q_off(tok, d0)]     = tf32r(e0[rr] * QSCALE);
                    base[q_off(tok, d0 + 1)] = tf32r(e1[rr] * QSCALE);
                } else if (z == 1) {
                    base[k_off(tok, d0)]     = tf32r(e0[rr]);
                    base[k_off(tok, d0 + 1)] = tf32r(e1[rr]);
                } else {
                    base[v_off(tok, d0)]     = tf32r(e0[rr]);
                    base[v_off(tok, d0 + 1)] = tf32r(e1[rr]);
                }
            }
        }
    }
}

// ---------------------------------------------------------------------------
// Kernel 2: fused flash attention, no-max softmax (ex2), pair-packed B frags.
// 256 thr = 8 warps; warp owns 16 q-rows, Q fragments resident in registers.
// KV tiles of 64 rows, 3-stage cp.async pipeline, all B loads LDS.128.
// ---------------------------------------------------------------------------
#define AT_NST 3
#define AT_STG 8192                       // floats per stage (K 4096 | V 4096)
#define AT_SMEM (AT_NST * AT_STG * 4)     // 98304 B
#define NITER (S_ / 64)                   // 32

__global__ __launch_bounds__(256, 2) void attn_mma(float* __restrict__ out)
{
    extern __shared__ float sm[];

    const int tid   = threadIdx.x;
    const int lane  = tid & 31;
    const int warp  = tid >> 5;
    const int qr    = lane >> 2;
    const int qc    = lane & 3;
    const int lbase = lane & ~3;

    const int b  = blockIdx.z;
    const int h  = blockIdx.y;
    const int q0 = blockIdx.x * 128;
    const int bh = b * H_ + h;

    const float* Kg = g_K + (size_t)bh * SHD;
    const float* Vg = g_V + (size_t)bh * SHD;
    const uint32_t smb = smem_u32(sm);

    // Q fragments: 8 x float4, resident for whole kernel.
    float4 qf[8];
    {
        const float* Qb = g_Q + (size_t)bh * SHD
                        + (size_t)((q0 >> 4) + warp) * 1024 + lane * 4;
#pragma unroll
        for (int kk = 0; kk < 8; ++kk)
            qf[kk] = *(const float4*)(Qb + kk * 128);
    }

    auto issue = [&](int t, int s) {
        uint32_t kd = smb + (uint32_t)(s * AT_STG) * 4 + tid * 64;
        const float* ks = Kg + t * 4096 + tid * 16;
#pragma unroll
        for (int i = 0; i < 4; ++i) CP16(kd + i * 16, ks + i * 4);
        uint32_t vd = kd + 4096 * 4;
        const float* vs = Vg + t * 4096 + tid * 16;
#pragma unroll
        for (int i = 0; i < 4; ++i) CP16(vd + i * 16, vs + i * 4);
    };

    issue(0, 0); CPCOMMIT();
    issue(1, 1); CPCOMMIT();

    float lp0 = 0.0f, lp1 = 0.0f;   // per-lane partial row sums
    float o[8][4];
#pragma unroll
    for (int n = 0; n < 8; ++n)
#pragma unroll
        for (int e = 0; e < 4; ++e) o[n][e] = 0.0f;

    for (int t = 0; t < NITER; ++t) {
        asm volatile("cp.async.wait_group 1;" ::: "memory");
        __syncthreads();
        if (t + 2 < NITER) issue(t + 2, (t + 2) % 3);
        CPCOMMIT();

        const float* Ks = sm + (t % 3) * AT_STG;
        const float* Vs = Ks + 4096;

#pragma unroll
        for (int half = 0; half < 2; ++half) {
            // ---- GEMM1: scores(16x32) = Q K^T ----
            float sc[4][4];
#pragma unroll
            for (int n = 0; n < 4; ++n)
#pragma unroll
                for (int e = 0; e < 4; ++e) sc[n][e] = 0.0f;

#pragma unroll
            for (int kkp = 0; kkp < 4; ++kkp) {
#pragma unroll
                for (int nt = 0; nt < 4; ++nt) {
                    float4 bb = *(const float4*)&Ks[(half * 4 + nt) * 512
                                                    + kkp * 128 + lane * 4];
                    mma8(sc[nt], (const float*)&qf[2 * kkp],     bb.x, bb.y);
                    mma8(sc[nt], (const float*)&qf[2 * kkp + 1], bb.z, bb.w);
                }
            }

            // ---- no-max softmax: p = 2^s (Q pre-scaled by log2e/8) ----
#pragma unroll
            for (int n = 0; n < 4; ++n) {
                float p0 = ex2f(sc[n][0]);
                float p1 = ex2f(sc[n][1]);
                float p2 = ex2f(sc[n][2]);
                float p3 = ex2f(sc[n][3]);
                lp0 += p0 + p1;
                lp1 += p2 + p3;
                sc[n][0] = tf32r(p0); sc[n][1] = tf32r(p1);
                sc[n][2] = tf32r(p2); sc[n][3] = tf32r(p3);
            }

            // ---- GEMM2: O += P V  (quad-shuffle C->A permutation) ----
#pragma unroll
            for (int ktl = 0; ktl < 4; ++ktl) {
                float a[4];
                {
                    float c0 = sc[ktl][0], c1 = sc[ktl][1];
                    float c2 = sc[ktl][2], c3 = sc[ktl][3];
                    int l0 = lbase + (qc >> 1);
                    int l1 = l0 + 2;
                    float x0 = __shfl_sync(0xffffffffu, c0, l0);
                    float x1 = __shfl_sync(0xffffffffu, c1, l0);
                    float y0 = __shfl_sync(0xffffffffu, c0, l1);
                    float y1 = __shfl_sync(0xffffffffu, c1, l1);
                    float z0 = __shfl_sync(0xffffffffu, c2, l0);
                    float z1 = __shfl_sync(0xffffffffu, c3, l0);
                    float w0 = __shfl_sync(0xffffffffu, c2, l1);
                    float w1 = __shfl_sync(0xffffffffu, c3, l1);
                    a[0] = (qc & 1) ? x1 : x0;
                    a[2] = (qc & 1) ? y1 : y0;
                    a[1] = (qc & 1) ? z1 : z0;
                    a[3] = (qc & 1) ? w1 : w0;
                }
#pragma unroll
                for (int ndp = 0; ndp < 4; ++ndp) {
                    float4 vv = *(const float4*)&Vs[(half * 4 + ktl) * 512
                                                    + ndp * 128 + lane * 4];
                    mma8(o[2 * ndp],     a, vv.x, vv.y);
                    mma8(o[2 * ndp + 1], a, vv.z, vv.w);
                }
            }
        }
    }

    // ---- deferred l reduction ----
    lp0 += __shfl_xor_sync(0xffffffffu, lp0, 1);
    lp0 += __shfl_xor_sync(0xffffffffu, lp0, 2);
    lp1 += __shfl_xor_sync(0xffffffffu, lp1, 1);
    lp1 += __shfl_xor_sync(0xffffffffu, lp1, 2);

    // ---- epilogue: normalize, write [B,S,D] ----
    {
        float inv0 = 1.0f / lp0;
        float inv1 = 1.0f / lp1;
        int r0 = q0 + warp * 16 + qr;
        int r1 = r0 + 8;
#pragma unroll
        for (int n = 0; n < 8; ++n) {
            int col = h * 64 + n * 8 + 2 * qc;
            float2 v0 = make_float2(o[n][0] * inv0, o[n][1] * inv0);
            float2 v1 = make_float2(o[n][2] * inv1, o[n][3] * inv1);
            *(float2*)&out[((size_t)b * S_ + r0) * D_ + col] = v0;
            *(float2*)&out[((size_t)b * S_ + r1) * D_ + col] = v1;
        }
    }
}

// ---------------------------------------------------------------------------
extern "C" void kernel_launch(void* const* d_in, const int* in_sizes, int n_in,
                              void* d_out, int out_size)
{
    const float* X  = (const float*)d_in[0];
    const float* Wq = (const float*)d_in[1];
    const float* bq = (const float*)d_in[2];
    const float* Wk = (const float*)d_in[3];
    const float* bk = (const float*)d_in[4];
    const float* Wv = (const float*)d_in[5];
    const float* bv = (const float*)d_in[6];
    float* out = (float*)d_out;

    cudaFuncSetAttribute(qkv_mma,
                         cudaFuncAttributeMaxDynamicSharedMemorySize, QK_SMEM);
    cudaFuncSetAttribute(attn_mma,
                         cudaFuncAttributeMaxDynamicSharedMemorySize, AT_SMEM);

    prep_round<<<(NX4 + 3 * NW4) / 256, 256>>>(X, Wq, Wk, Wv);

    dim3 g1(D_ / 128, (B_ * S_) / 128, 3);   // (6, 64, 3)
    qkv_mma<<<g1, 256, QK_SMEM>>>(bq, bk, bv);

    dim3 g2(S_ / 128, H_, B_);               // (16, 12, 4)
    attn_mma<<<g2, 256, AT_SMEM>>>(out);
}

// round 9
// speedup vs baseline: 1.0338x; 1.0338x over previous
#include <cuda_runtime.h>
#include <math.h>
#include <cstdint>

#define B_  4
#define S_  2048
#define D_  768
#define H_  12
#define HD_ 64
#define SHD (S_ * HD_)          // 131072 floats per (b,h)

// Device-global scratch (cudaMalloc forbidden).
// g_Q: A-frag packed      [bh][mt(128)][kk(8)][lane(32)][4]   (pre-scaled log2e/8)
// g_K: B-frag pair-packed [bh][nt(256)][kkp(4)][lane(32)][4]
// g_V: B-frag pair-packed [bh][kt(256)][ndp(4)][lane(32)][4]
// g_Xp: X in A-frag order [rb(512)][kk(96)][lane(32)][4]      (tf32-rounded)
// g_Wp: W pair-packed B   [z][nbp(48)][kk(96)][lane(32)][4]   (tf32-rounded)
__device__ float g_Q[B_ * H_ * SHD];
__device__ float g_K[B_ * H_ * SHD];
__device__ float g_V[B_ * H_ * SHD];
__device__ float g_Xp[B_ * S_ * D_];
__device__ float g_Wp[3 * D_ * D_];

// ---------------------------------------------------------------------------
__device__ __forceinline__ float tf32r(float x) {
    uint32_t u;
    asm("cvt.rna.tf32.f32 %0, %1;" : "=r"(u) : "f"(x));
    return __uint_as_float(u);
}
__device__ __forceinline__ float ex2f(float x) {
    float y;
    asm("ex2.approx.f32 %0, %1;" : "=f"(y) : "f"(x));
    return y;
}
__device__ __forceinline__ void mma8(float* d, const float* a, float b0, float b1) {
    asm volatile(
        "mma.sync.aligned.m16n8k8.row.col.f32.tf32.tf32.f32 "
        "{%0,%1,%2,%3}, {%4,%5,%6,%7}, {%8,%9}, {%0,%1,%2,%3};"
        : "+f"(d[0]), "+f"(d[1]), "+f"(d[2]), "+f"(d[3])
        : "r"(__float_as_uint(a[0])), "r"(__float_as_uint(a[1])),
          "r"(__float_as_uint(a[2])), "r"(__float_as_uint(a[3])),
          "r"(__float_as_uint(b0)), "r"(__float_as_uint(b1)));
}
__device__ __forceinline__ uint32_t smem_u32(const void* p) {
    uint32_t a;
    asm("{ .reg .u64 t; cvta.to.shared.u64 t, %1; cvt.u32.u64 %0, t; }" : "=r"(a) : "l"(p));
    return a;
}
#define CP16(dst, src) \
    asm volatile("cp.async.cg.shared.global [%0], [%1], 16;" :: "r"(dst), "l"(src) : "memory")
#define CPCOMMIT() asm volatile("cp.async.commit_group;" ::: "memory")

// fragment-pack offset helpers; tok in [0,2048), d in [0,64)
__device__ __forceinline__ int q_off(int tok, int d) {
    int mt = tok >> 4, qr = tok & 7, half = (tok >> 3) & 1;
    int kk = d >> 3, qc = d & 3, colh = (d >> 2) & 1;
    return mt * 1024 + kk * 128 + (qr * 4 + qc) * 4 + half + 2 * colh;
}
__device__ __forceinline__ int k_off(int tok, int d) {
    int nt = tok >> 3, qr = tok & 7;
    int kk = d >> 3, qc = d & 3, sl = (d >> 2) & 1;
    int kkp = kk >> 1, par = kk & 1;
    return nt * 512 + kkp * 128 + (qr * 4 + qc) * 4 + par * 2 + sl;
}
__device__ __forceinline__ int v_off(int tok, int d) {
    int kt = tok >> 3, qcv = tok & 3, sl = (tok >> 2) & 1;
    int nd = d >> 3, qrv = d & 7;
    int ndp = nd >> 1, par = nd & 1;
    return kt * 512 + ndp * 128 + (qrv * 4 + qcv) * 4 + par * 2 + sl;
}
// X A-frag pack: row r in [0,8192), col k in [0,768)
__device__ __forceinline__ int x_off(int r, int k) {
    int rb = r >> 4, qr = r & 7, half = (r >> 3) & 1;
    int kk = k >> 3, qc = k & 3, colh = (k >> 2) & 1;
    return rb * (96 * 128) + kk * 128 + (qr * 4 + qc) * 4 + half + 2 * colh;
}
// W pair-packed B-frag: k in [0,768), n in [0,768)
__device__ __forceinline__ int w_off(int k, int n) {
    int nb = n >> 3, qr = n & 7;
    int kk = k >> 3, qc = k & 3, sl = (k >> 2) & 1;
    return (nb >> 1) * (96 * 128) + kk * 128 + (qr * 4 + qc) * 4 + (nb & 1) * 2 + sl;
}

// ---------------------------------------------------------------------------
// Kernel 0: round X/W to tf32 and scatter into fragment-packed layouts.
// ---------------------------------------------------------------------------
#define NX4 ((B_ * S_ * D_) / 4)   // 1572864
#define NW4 ((D_ * D_) / 4)        // 147456

__global__ __launch_bounds__(256) void prep_round(
    const float* __restrict__ X, const float* __restrict__ Wq,
    const float* __restrict__ Wk, const float* __restrict__ Wv)
{
    int i = blockIdx.x * 256 + threadIdx.x;
    if (i < NX4) {
        int r = i / 192, k4 = i - r * 192;
        int k = k4 * 4;
        float4 v = ((const float4*)X)[i];
        int base = x_off(r, k);            // k%4==0: elements at +0,+4,+8,+12
        g_Xp[base]      = tf32r(v.x);
        g_Xp[base + 4]  = tf32r(v.y);
        g_Xp[base + 8]  = tf32r(v.z);
        g_Xp[base + 12] = tf32r(v.w);
    } else {
        int j = i - NX4;
        int z = j / NW4, rr = j - z * NW4;
        int k = rr / 192, n4 = rr - k * 192;
        int n = n4 * 4;
        const float4* src = (const float4*)((z == 0) ? Wq : (z == 1) ? Wk : Wv);
        float4 v = src[rr];
        float* out = g_Wp + (size_t)z * (48 * 96 * 128);
        out[w_off(k, n)]     = tf32r(v.x);
        out[w_off(k, n + 1)] = tf32r(v.y);
        out[w_off(k, n + 2)] = tf32r(v.z);
        out[w_off(k, n + 3)] = tf32r(v.w);
    }
}

// ---------------------------------------------------------------------------
// Kernel 1: QKV projection, tf32 mma.sync, fragment-packed operands.
// Stage: X slice [rb(8)][kk(4)][128] 16KB + W slice [nbp(8)][kk(4)][128] 16KB.
// 3-stage cp.async. All smem fragment loads are LDS.128.
// ---------------------------------------------------------------------------
#define QK_STG 8192                       // floats per stage (X 4096 | W 4096)
#define QK_SMEM (3 * QK_STG * 4)          // 98304 B

__global__ __launch_bounds__(256) void qkv_mma(
    const float* __restrict__ bq, const float* __restrict__ bk,
    const float* __restrict__ bv)
{
    extern __shared__ float smx[];

    const int tid  = threadIdx.x;
    const int lane = tid & 31;
    const int warp = tid >> 5;
    const int qr   = lane >> 2;
    const int qc   = lane & 3;
    const int wm   = warp >> 2;    // 0..1
    const int wn   = warp & 3;     // 0..3

    const int row0 = blockIdx.y * 128;
    const int col0 = blockIdx.x * 128;
    const int z    = blockIdx.z;

    const float* bias = (z == 0) ? bq : (z == 1) ? bk : bv;
    float* out        = (z == 0) ? g_Q : (z == 1) ? g_K : g_V;

    const uint32_t smb = smem_u32(smx);
    const float* gX = g_Xp + (size_t)(row0 >> 4) * (96 * 128);
    const float* gW = g_Wp + (size_t)z * (48 * 96 * 128)
                    + (size_t)(col0 >> 4) * (96 * 128);

    const int sub = tid >> 5;        // 0..7: rb / nbp index
    const int t32 = tid & 31;

    auto issue = [&](int it, int s) {
        uint32_t xb = smb + (uint32_t)(s * QK_STG) * 4;
        const float* xsrc = gX + (size_t)sub * (96 * 128) + it * 512 + t32 * 4;
        const float* wsrc = gW + (size_t)sub * (96 * 128) + it * 512 + t32 * 4;
        uint32_t xd = xb + (uint32_t)(sub * 512 + t32 * 4) * 4;
        uint32_t wd = xd + 4096 * 4;
#pragma unroll
        for (int p = 0; p < 4; ++p) {
            CP16(xd + p * 512, xsrc + p * 128);
            CP16(wd + p * 512, wsrc + p * 128);
        }
    };

    float acc[4][4][4];
#pragma unroll
    for (int m = 0; m < 4; ++m)
#pragma unroll
        for (int n = 0; n < 4; ++n)
#pragma unroll
            for (int e = 0; e < 4; ++e) acc[m][n][e] = 0.0f;

    issue(0, 0); CPCOMMIT();
    issue(1, 1); CPCOMMIT();

    for (int it = 0; it < 24; ++it) {
        asm volatile("cp.async.wait_group 1;" ::: "memory");
        __syncthreads();
        if (it + 2 < 24) issue(it + 2, (it + 2) % 3);
        CPCOMMIT();

        const float* Xs = smx + (it % 3) * QK_STG;
        const float* Ws = Xs + 4096;

#pragma unroll
        for (int kk = 0; kk < 4; ++kk) {
            float4 a[4];
#pragma unroll
            for (int mt = 0; mt < 4; ++mt)
                a[mt] = *(const float4*)&Xs[((wm * 4 + mt) * 4 + kk) * 128 + lane * 4];
#pragma unroll
            for (int ntp = 0; ntp < 2; ++ntp) {
                float4 bb = *(const float4*)&Ws[((wn * 2 + ntp) * 4 + kk) * 128 + lane * 4];
#pragma unroll
                for (int mt = 0; mt < 4; ++mt) {
                    mma8(acc[mt][2 * ntp],     (const float*)&a[mt], bb.x, bb.y);
                    mma8(acc[mt][2 * ntp + 1], (const float*)&a[mt], bb.z, bb.w);
                }
            }
        }
    }

    // Epilogue: bias (+log2e/8 scale for Q), tf32 round, fragment-packed scatter.
    const float QSCALE = 0.18033688f;   // log2(e) / 8
#pragma unroll
    for (int mt = 0; mt < 4; ++mt) {
        int r0 = row0 + wm * 64 + mt * 16 + qr;
#pragma unroll
        for (int nt = 0; nt < 4; ++nt) {
            int gc = col0 + wn * 32 + nt * 8 + 2 * qc;
            int hh = gc >> 6, d0 = gc & 63;
            float bv0 = bias[gc], bv1 = bias[gc + 1];
            float e0[2] = { acc[mt][nt][0] + bv0, acc[mt][nt][2] + bv0 };
            float e1[2] = { acc[mt][nt][1] + bv1, acc[mt][nt][3] + bv1 };
#pragma unroll
            for (int rr = 0; rr < 2; ++rr) {
                int r = r0 + rr * 8;
                int bb = r >> 11, tok = r & (S_ - 1);
                float* base = out + ((size_t)bb * H_ + hh) * SHD;
                if (z == 0) {
                    base[q_off(tok, d0)]     = tf32r(e0[rr] * QSCALE);
                    base[q_off(tok, d0 + 1)] = tf32r(e1[rr] * QSCALE);
                } else if (z == 1) {
                    base[k_off(tok, d0)]     = tf32r(e0[rr]);
                    base[k_off(tok, d0 + 1)] = tf32r(e1[rr]);
                } else {
                    base[v_off(tok, d0)]     = tf32r(e0[rr]);
                    base[v_off(tok, d0 + 1)] = tf32r(e1[rr]);
                }
            }
        }
    }
}

// ---------------------------------------------------------------------------
// Kernel 2: fused flash attention (unchanged from R8).
// ---------------------------------------------------------------------------
#define AT_NST 3
#define AT_STG 8192                       // floats per stage (K 4096 | V 4096)
#define AT_SMEM (AT_NST * AT_STG * 4)     // 98304 B
#define NITER (S_ / 64)                   // 32

__global__ __launch_bounds__(256, 2) void attn_mma(float* __restrict__ out)
{
    extern __shared__ float sm[];

    const int tid   = threadIdx.x;
    const int lane  = tid & 31;
    const int warp  = tid >> 5;
    const int qr    = lane >> 2;
    const int qc    = lane & 3;
    const int lbase = lane & ~3;

    const int b  = blockIdx.z;
    const int h  = blockIdx.y;
    const int q0 = blockIdx.x * 128;
    const int bh = b * H_ + h;

    const float* Kg = g_K + (size_t)bh * SHD;
    const float* Vg = g_V + (size_t)bh * SHD;
    const uint32_t smb = smem_u32(sm);

    float4 qf[8];
    {
        const float* Qb = g_Q + (size_t)bh * SHD
                        + (size_t)((q0 >> 4) + warp) * 1024 + lane * 4;
#pragma unroll
        for (int kk = 0; kk < 8; ++kk)
            qf[kk] = *(const float4*)(Qb + kk * 128);
    }

    auto issue = [&](int t, int s) {
        uint32_t kd = smb + (uint32_t)(s * AT_STG) * 4 + tid * 64;
        const float* ks = Kg + t * 4096 + tid * 16;
#pragma unroll
        for (int i = 0; i < 4; ++i) CP16(kd + i * 16, ks + i * 4);
        uint32_t vd = kd + 4096 * 4;
        const float* vs = Vg + t * 4096 + tid * 16;
#pragma unroll
        for (int i = 0; i < 4; ++i) CP16(vd + i * 16, vs + i * 4);
    };

    issue(0, 0); CPCOMMIT();
    issue(1, 1); CPCOMMIT();

    float lp0 = 0.0f, lp1 = 0.0f;
    float o[8][4];
#pragma unroll
    for (int n = 0; n < 8; ++n)
#pragma unroll
        for (int e = 0; e < 4; ++e) o[n][e] = 0.0f;

    for (int t = 0; t < NITER; ++t) {
        asm volatile("cp.async.wait_group 1;" ::: "memory");
        __syncthreads();
        if (t + 2 < NITER) issue(t + 2, (t + 2) % 3);
        CPCOMMIT();

        const float* Ks = sm + (t % 3) * AT_STG;
        const float* Vs = Ks + 4096;

#pragma unroll
        for (int half = 0; half < 2; ++half) {
            float sc[4][4];
#pragma unroll
            for (int n = 0; n < 4; ++n)
#pragma unroll
                for (int e = 0; e < 4; ++e) sc[n][e] = 0.0f;

#pragma unroll
            for (int kkp = 0; kkp < 4; ++kkp) {
#pragma unroll
                for (int nt = 0; nt < 4; ++nt) {
                    float4 bb = *(const float4*)&Ks[(half * 4 + nt) * 512
                                                    + kkp * 128 + lane * 4];
                    mma8(sc[nt], (const float*)&qf[2 * kkp],     bb.x, bb.y);
                    mma8(sc[nt], (const float*)&qf[2 * kkp + 1], bb.z, bb.w);
                }
            }

#pragma unroll
            for (int n = 0; n < 4; ++n) {
                float p0 = ex2f(sc[n][0]);
                float p1 = ex2f(sc[n][1]);
                float p2 = ex2f(sc[n][2]);
                float p3 = ex2f(sc[n][3]);
                lp0 += p0 + p1;
                lp1 += p2 + p3;
                sc[n][0] = tf32r(p0); sc[n][1] = tf32r(p1);
                sc[n][2] = tf32r(p2); sc[n][3] = tf32r(p3);
            }

#pragma unroll
            for (int ktl = 0; ktl < 4; ++ktl) {
                float a[4];
                {
                    float c0 = sc[ktl][0], c1 = sc[ktl][1];
                    float c2 = sc[ktl][2], c3 = sc[ktl][3];
                    int l0 = lbase + (qc >> 1);
                    int l1 = l0 + 2;
                    float x0 = __shfl_sync(0xffffffffu, c0, l0);
                    float x1 = __shfl_sync(0xffffffffu, c1, l0);
                    float y0 = __shfl_sync(0xffffffffu, c0, l1);
                    float y1 = __shfl_sync(0xffffffffu, c1, l1);
                    float z0 = __shfl_sync(0xffffffffu, c2, l0);
                    float z1 = __shfl_sync(0xffffffffu, c3, l0);
                    float w0 = __shfl_sync(0xffffffffu, c2, l1);
                    float w1 = __shfl_sync(0xffffffffu, c3, l1);
                    a[0] = (qc & 1) ? x1 : x0;
                    a[2] = (qc & 1) ? y1 : y0;
                    a[1] = (qc & 1) ? z1 : z0;
                    a[3] = (qc & 1) ? w1 : w0;
                }
#pragma unroll
                for (int ndp = 0; ndp < 4; ++ndp) {
                    float4 vv = *(const float4*)&Vs[(half * 4 + ktl) * 512
                                                    + ndp * 128 + lane * 4];
                    mma8(o[2 * ndp],     a, vv.x, vv.y);
                    mma8(o[2 * ndp + 1], a, vv.z, vv.w);
                }
            }
        }
    }

    lp0 += __shfl_xor_sync(0xffffffffu, lp0, 1);
    lp0 += __shfl_xor_sync(0xffffffffu, lp0, 2);
    lp1 += __shfl_xor_sync(0xffffffffu, lp1, 1);
    lp1 += __shfl_xor_sync(0xffffffffu, lp1, 2);

    {
        float inv0 = 1.0f / lp0;
        float inv1 = 1.0f / lp1;
        int r0 = q0 + warp * 16 + qr;
        int r1 = r0 + 8;
#pragma unroll
        for (int n = 0; n < 8; ++n) {
            int col = h * 64 + n * 8 + 2 * qc;
            float2 v0 = make_float2(o[n][0] * inv0, o[n][1] * inv0);
            float2 v1 = make_float2(o[n][2] * inv1, o[n][3] * inv1);
            *(float2*)&out[((size_t)b * S_ + r0) * D_ + col] = v0;
            *(float2*)&out[((size_t)b * S_ + r1) * D_ + col] = v1;
        }
    }
}

// ---------------------------------------------------------------------------
extern "C" void kernel_launch(void* const* d_in, const int* in_sizes, int n_in,
                              void* d_out, int out_size)
{
    const float* X  = (const float*)d_in[0];
    const float* Wq = (const float*)d_in[1];
    const float* bq = (const float*)d_in[2];
    const float* Wk = (const float*)d_in[3];
    const float* bk = (const float*)d_in[4];
    const float* Wv = (const float*)d_in[5];
    const float* bv = (const float*)d_in[6];
    float* out = (float*)d_out;

    cudaFuncSetAttribute(qkv_mma,
                         cudaFuncAttributeMaxDynamicSharedMemorySize, QK_SMEM);
    cudaFuncSetAttribute(attn_mma,
                         cudaFuncAttributeMaxDynamicSharedMemorySize, AT_SMEM);

    prep_round<<<(NX4 + 3 * NW4) / 256, 256>>>(X, Wq, Wk, Wv);

    dim3 g1(D_ / 128, (B_ * S_) / 128, 3);   // (6, 64, 3)
    qkv_mma<<<g1, 256, QK_SMEM>>>(bq, bk, bv);

    dim3 g2(S_ / 128, H_, B_);               // (16, 12, 4)
    attn_mma<<<g2, 256, AT_SMEM>>>(out);
}

// round 10
// speedup vs baseline: 2.0008x; 1.9355x over previous
#include <cuda_runtime.h>
#include <cuda_fp16.h>
#include <math.h>
#include <cstdint>

#define B_  4
#define S_  2048
#define D_  768
#define H_  12
#define HD_ 64
#define UQ_BH 65536             // uint32 (=half2) per (b,h) tensor

// Device-global scratch (cudaMalloc forbidden).  All fp16, packed as uint32.
// g_Q: A-frag m16n8k16  [bh][mt(128)][kb(4)][lane(32)][reg(4)]    (pre-scaled log2e/8)
// g_K: B-frag, kb-paired [bh][nt(256)][kbp(2)][lane(32)][4]
// g_V: B-frag, nd-paired [bh][kt(128)][ndp(4)][lane(32)][4]
// g_Xp: X A-frag         [rblk(64)][kbp(24)][mt8(8)][kpar(2)][lane][4]
// g_Wp: W B-frag         [z*6+cblk][kbp(24)][nb(16)][lane][4]
__device__ uint32_t g_Q[48 * UQ_BH];
__device__ uint32_t g_K[48 * UQ_BH];
__device__ uint32_t g_V[48 * UQ_BH];
__device__ uint32_t g_Xp[64 * 24 * 2048];
__device__ uint32_t g_Wp[18 * 24 * 2048];

// ---------------------------------------------------------------------------
__device__ __forceinline__ float ex2f(float x) {
    float y;
    asm("ex2.approx.f32 %0, %1;" : "=f"(y) : "f"(x));
    return y;
}
__device__ __forceinline__ uint32_t h2pack(float a, float b) {
    __half2 h = __floats2half2_rn(a, b);
    return *(uint32_t*)&h;
}
__device__ __forceinline__ void mma16(float* d, const uint32_t* a,
                                      uint32_t b0, uint32_t b1) {
    asm volatile(
        "mma.sync.aligned.m16n8k16.row.col.f32.f16.f16.f32 "
        "{%0,%1,%2,%3},{%4,%5,%6,%7},{%8,%9},{%0,%1,%2,%3};"
        : "+f"(d[0]), "+f"(d[1]), "+f"(d[2]), "+f"(d[3])
        : "r"(a[0]), "r"(a[1]), "r"(a[2]), "r"(a[3]), "r"(b0), "r"(b1));
}
__device__ __forceinline__ uint32_t smem_u32(const void* p) {
    uint32_t a;
    asm("{ .reg .u64 t; cvta.to.shared.u64 t, %1; cvt.u32.u64 %0, t; }" : "=r"(a) : "l"(p));
    return a;
}
#define CP16(dst, src) \
    asm volatile("cp.async.cg.shared.global [%0], [%1], 16;" :: "r"(dst), "l"(src) : "memory")
#define CPCOMMIT() asm volatile("cp.async.commit_group;" ::: "memory")

// ---------------------------------------------------------------------------
// Kernel 0: convert X/W fp32 -> fp16 fragment layouts.
// ---------------------------------------------------------------------------
#define NXT (8192 * 48)           // X threads: (row, kb)
#define NWT (3 * 384 * 192)       // W threads: (z, kpair, n4)

__global__ __launch_bounds__(256) void prep_pack(
    const float* __restrict__ X, const float* __restrict__ Wq,
    const float* __restrict__ Wk, const float* __restrict__ Wv)
{
    int i = blockIdx.x * 256 + threadIdx.x;
    if (i < NXT) {
        int r = i / 48, kb = i - r * 48;
        int rblk = r >> 7, mt8 = (r >> 4) & 7, qr = r & 7, rowh = (r >> 3) & 1;
        int kbp = kb >> 1, kpar = kb & 1;
        int B0 = ((((rblk * 24 + kbp) * 8 + mt8) * 2 + kpar) * 32 + qr * 4) * 4 + rowh;
        const float* xs = X + (size_t)r * D_ + kb * 16;
#pragma unroll
        for (int j = 0; j < 4; ++j) {
            float4 v = ((const float4*)xs)[j];
            int colh = j >> 1;
            int qc0 = (2 * j) & 3, qc1 = (2 * j + 1) & 3;
            g_Xp[B0 + qc0 * 4 + 2 * colh] = h2pack(v.x, v.y);
            g_Xp[B0 + qc1 * 4 + 2 * colh] = h2pack(v.z, v.w);
        }
    } else if (i < NXT + NWT) {
        int j = i - NXT;
        int z = j / 73728, rr = j - z * 73728;
        int kp = rr / 192, n4 = rr - kp * 192;
        int n0 = n4 * 4, k = 2 * kp;
        int kb = k >> 4, kbp = kb >> 1, kpar = kb & 1;
        int qc = kp & 3, kh = (kp >> 2) & 1;
        const float* Wsrc = (z == 0) ? Wq : (z == 1) ? Wk : Wv;
        float4 va = *(const float4*)&Wsrc[(size_t)k * D_ + n0];
        float4 vb = *(const float4*)&Wsrc[(size_t)(k + 1) * D_ + n0];
        float a_[4] = { va.x, va.y, va.z, va.w };
        float b_[4] = { vb.x, vb.y, vb.z, vb.w };
#pragma unroll
        for (int t = 0; t < 4; ++t) {
            int n = n0 + t;
            int cblk = n >> 7, nbl = (n & 127) >> 3, qr = n & 7;
            int idx = ((((z * 6 + cblk) * 24 + kbp) * 16 + nbl) * 32 + qr * 4 + qc) * 4
                    + (kh + 2 * kpar);
            g_Wp[idx] = h2pack(a_[t], b_[t]);
        }
    }
}

// ---------------------------------------------------------------------------
// Kernel 1: QKV projection, fp16 m16n8k16, fp32 accum, cp.async 3-stage.
// Stage = X chunk 8KB + W chunk 8KB (one kbp = k32).  24 stages.
// ---------------------------------------------------------------------------
#define QK_STGU 4096                      // uints/stage
#define QK_SMEM (3 * QK_STGU * 4)         // 49152 B

__global__ __launch_bounds__(256) void qkv_mma(
    const float* __restrict__ bq, const float* __restrict__ bk,
    const float* __restrict__ bv)
{
    extern __shared__ uint32_t smu[];

    const int tid  = threadIdx.x;
    const int lane = tid & 31;
    const int warp = tid >> 5;
    const int qr   = lane >> 2;
    const int qc   = lane & 3;
    const int wm   = warp >> 2;    // 0..1
    const int wn   = warp & 3;     // 0..3

    const int row0 = blockIdx.y * 128;
    const int col0 = blockIdx.x * 128;
    const int z    = blockIdx.z;

    const float* bias = (z == 0) ? bq : (z == 1) ? bk : bv;

    const uint32_t smb = smem_u32(smu);
    const uint32_t* gX = g_Xp + (size_t)blockIdx.y * (24 * 2048);
    const uint32_t* gW = g_Wp + (size_t)(z * 6 + blockIdx.x) * (24 * 2048);

    auto issue = [&](int it, int s) {
        uint32_t xd = smb + (uint32_t)(s * QK_STGU + tid * 4) * 4;
        const uint32_t* xs = gX + it * 2048 + tid * 4;
        CP16(xd, xs); CP16(xd + 4096, xs + 1024);
        uint32_t wd = xd + 2048 * 4;
        const uint32_t* ws = gW + it * 2048 + tid * 4;
        CP16(wd, ws); CP16(wd + 4096, ws + 1024);
    };

    float acc[4][4][4];
#pragma unroll
    for (int m = 0; m < 4; ++m)
#pragma unroll
        for (int n = 0; n < 4; ++n)
#pragma unroll
            for (int e = 0; e < 4; ++e) acc[m][n][e] = 0.0f;

    issue(0, 0); CPCOMMIT();
    issue(1, 1); CPCOMMIT();

    for (int it = 0; it < 24; ++it) {
        asm volatile("cp.async.wait_group 1;" ::: "memory");
        __syncthreads();
        if (it + 2 < 24) issue(it + 2, (it + 2) % 3);
        CPCOMMIT();

        const uint32_t* Xs = smu + (it % 3) * QK_STGU;
        const uint32_t* Ws = Xs + 2048;

        uint4 bF[4];
#pragma unroll
        for (int nt = 0; nt < 4; ++nt)
            bF[nt] = *(const uint4*)&Ws[((wn * 4 + nt) * 32 + lane) * 4];

#pragma unroll
        for (int kpar = 0; kpar < 2; ++kpar) {
            uint4 aF[4];
#pragma unroll
            for (int mt = 0; mt < 4; ++mt)
                aF[mt] = *(const uint4*)&Xs[(((wm * 4 + mt) * 2 + kpar) * 32 + lane) * 4];
#pragma unroll
            for (int nt = 0; nt < 4; ++nt) {
                uint32_t b0 = kpar ? bF[nt].z : bF[nt].x;
                uint32_t b1 = kpar ? bF[nt].w : bF[nt].y;
#pragma unroll
                for (int mt = 0; mt < 4; ++mt)
                    mma16(acc[mt][nt], (const uint32_t*)&aF[mt], b0, b1);
            }
        }
    }

    // Epilogue: bias, pack fp16, fragment-layout scatter to g_Q/g_K/g_V.
    const float QSCALE = 0.18033688f;   // log2(e)/8
    const int bIdx = row0 >> 11;
#pragma unroll
    for (int mt = 0; mt < 4; ++mt) {
        int rowbaseS = (row0 & 2047) + wm * 64 + mt * 16;
        int mtQ = rowbaseS >> 4;
#pragma unroll
        for (int nt = 0; nt < 4; ++nt) {
            int gc = col0 + wn * 32 + nt * 8 + 2 * qc;
            int hh = gc >> 6, d0 = gc & 63;
            int bh = bIdx * H_ + hh;
            float bv0 = bias[gc], bv1 = bias[gc + 1];
            float e0[2] = { acc[mt][nt][0] + bv0, acc[mt][nt][2] + bv0 };
            float e1[2] = { acc[mt][nt][1] + bv1, acc[mt][nt][3] + bv1 };
#pragma unroll
            for (int rr = 0; rr < 2; ++rr) {
                if (z == 0) {
                    int kb = d0 >> 4, colh = (d0 >> 3) & 1;
                    int idx = ((mtQ * 4 + kb) * 32 + lane) * 4 + (rr + 2 * colh);
                    g_Q[(size_t)bh * UQ_BH + idx] =
                        h2pack(e0[rr] * QSCALE, e1[rr] * QSCALE);
                } else if (z == 1) {
                    int ntK = (rowbaseS >> 3) + rr;
                    int kbK = d0 >> 4, kbp = kbK >> 1, kpar = kbK & 1;
                    int kh = (d0 >> 3) & 1;
                    int idx = ((ntK * 2 + kbp) * 32 + lane) * 4 + (kh + 2 * kpar);
                    g_K[(size_t)bh * UQ_BH + idx] = h2pack(e0[rr], e1[rr]);
                } else {
                    // V: pairs run along token -> two 16-bit stores
                    int tokc = rr * 8 + qr;          // tok & 15
                    int qc_t = qr >> 1, eT = qr & 1, kh = rr;
                    __half* vb = (__half*)g_V + (size_t)bh * (UQ_BH * 2);
#pragma unroll
                    for (int dd = 0; dd < 2; ++dd) {
                        int d = d0 + dd;
                        int nd = d >> 3, ndp = nd >> 1, ndpar = nd & 1;
                        int qr_d = d & 7;
                        int idx = ((mtQ * 4 + ndp) * 32 + qr_d * 4 + qc_t) * 4
                                + (kh + 2 * ndpar);
                        vb[idx * 2 + eT] = __float2half_rn(dd ? e1[rr] : e0[rr]);
                    }
                }
            }
        }
    }
}

// ---------------------------------------------------------------------------
// Kernel 2: fused flash attention, fp16 m16n8k16, no-max ex2 softmax.
// 256 thr = 8 warps x 16 q-rows.  64-token KV tiles, 3-stage cp.async.
// P C-frag -> A-frag is a pure in-lane fp16 pack (no shuffles).
// ---------------------------------------------------------------------------
#define AT_STGU 4096                      // uints/stage (K 2048 | V 2048)
#define AT_SMEM (3 * AT_STGU * 4)         // 49152 B
#define NITER (S_ / 64)                   // 32

__global__ __launch_bounds__(256) void attn_mma(float* __restrict__ out)
{
    extern __shared__ uint32_t smu[];

    const int tid  = threadIdx.x;
    const int lane = tid & 31;
    const int warp = tid >> 5;
    const int qr   = lane >> 2;
    const int qc   = lane & 3;

    const int b  = blockIdx.z;
    const int h  = blockIdx.y;
    const int q0 = blockIdx.x * 128;
    const int bh = b * H_ + h;

    const uint32_t* Kg = g_K + (size_t)bh * UQ_BH;
    const uint32_t* Vg = g_V + (size_t)bh * UQ_BH;
    const uint32_t smb = smem_u32(smu);

    // Q fragments resident: qf[kb][4]
    uint32_t qf[4][4];
    {
        const uint32_t* Qb = g_Q + (size_t)bh * UQ_BH
                           + (size_t)((q0 >> 4) + warp) * 512 + lane * 4;
#pragma unroll
        for (int kb = 0; kb < 4; ++kb)
            *(uint4*)qf[kb] = *(const uint4*)(Qb + kb * 128);
    }

    auto issue = [&](int t, int s) {
        uint32_t kd = smb + (uint32_t)(s * AT_STGU + tid * 8) * 4;
        const uint32_t* ks = Kg + t * 2048 + tid * 8;
        CP16(kd, ks); CP16(kd + 16, ks + 4);
        uint32_t vd = kd + 2048 * 4;
        const uint32_t* vs = Vg + t * 2048 + tid * 8;
        CP16(vd, vs); CP16(vd + 16, vs + 4);
    };

    issue(0, 0); CPCOMMIT();
    issue(1, 1); CPCOMMIT();

    float lp0 = 0.0f, lp1 = 0.0f;
    float o[8][4];
#pragma unroll
    for (int n = 0; n < 8; ++n)
#pragma unroll
        for (int e = 0; e < 4; ++e) o[n][e] = 0.0f;

    for (int t = 0; t < NITER; ++t) {
        asm volatile("cp.async.wait_group 1;" ::: "memory");
        __syncthreads();
        if (t + 2 < NITER) issue(t + 2, (t + 2) % 3);
        CPCOMMIT();

        const uint32_t* Ks = smu + (t % 3) * AT_STGU;
        const uint32_t* Vs = Ks + 2048;

        // ---- GEMM1: scores(16x64) = Q K^T ----
        float sc[8][4];
#pragma unroll
        for (int n = 0; n < 8; ++n)
#pragma unroll
            for (int e = 0; e < 4; ++e) sc[n][e] = 0.0f;

#pragma unroll
        for (int ntL = 0; ntL < 8; ++ntL) {
#pragma unroll
            for (int kbp = 0; kbp < 2; ++kbp) {
                uint4 u = *(const uint4*)&Ks[((ntL * 2 + kbp) * 32 + lane) * 4];
                mma16(sc[ntL], qf[2 * kbp],     u.x, u.y);
                mma16(sc[ntL], qf[2 * kbp + 1], u.z, u.w);
            }
        }

        // ---- no-max softmax: p = 2^s; pack to fp16 A-frags in-lane ----
        uint32_t pp[8][2];
#pragma unroll
        for (int n = 0; n < 8; ++n) {
            float p0 = ex2f(sc[n][0]);
            float p1 = ex2f(sc[n][1]);
            float p2 = ex2f(sc[n][2]);
            float p3 = ex2f(sc[n][3]);
            lp0 += p0 + p1;
            lp1 += p2 + p3;
            pp[n][0] = h2pack(p0, p1);
            pp[n][1] = h2pack(p2, p3);
        }

        // ---- GEMM2: O += P V ----
#pragma unroll
        for (int ktL = 0; ktL < 4; ++ktL) {
            uint32_t a[4] = { pp[2 * ktL][0],     pp[2 * ktL][1],
                              pp[2 * ktL + 1][0], pp[2 * ktL + 1][1] };
#pragma unroll
            for (int ndp = 0; ndp < 4; ++ndp) {
                uint4 u = *(const uint4*)&Vs[((ktL * 4 + ndp) * 32 + lane) * 4];
                mma16(o[2 * ndp],     a, u.x, u.y);
                mma16(o[2 * ndp + 1], a, u.z, u.w);
            }
        }
    }

    // ---- deferred l reduction ----
    lp0 += __shfl_xor_sync(0xffffffffu, lp0, 1);
    lp0 += __shfl_xor_sync(0xffffffffu, lp0, 2);
    lp1 += __shfl_xor_sync(0xffffffffu, lp1, 1);
    lp1 += __shfl_xor_sync(0xffffffffu, lp1, 2);

    // ---- epilogue: normalize, write [B,S,D] fp32 ----
    {
        float inv0 = 1.0f / lp0;
        float inv1 = 1.0f / lp1;
        int r0 = q0 + warp * 16 + qr;
        int r1 = r0 + 8;
#pragma unroll
        for (int n = 0; n < 8; ++n) {
            int col = h * 64 + n * 8 + 2 * qc;
            float2 v0 = make_float2(o[n][0] * inv0, o[n][1] * inv0);
            float2 v1 = make_float2(o[n][2] * inv1, o[n][3] * inv1);
            *(float2*)&out[((size_t)b * S_ + r0) * D_ + col] = v0;
            *(float2*)&out[((size_t)b * S_ + r1) * D_ + col] = v1;
        }
    }
}

// ---------------------------------------------------------------------------
extern "C" void kernel_launch(void* const* d_in, const int* in_sizes, int n_in,
                              void* d_out, int out_size)
{
    const float* X  = (const float*)d_in[0];
    const float* Wq = (const float*)d_in[1];
    const float* bq = (const float*)d_in[2];
    const float* Wk = (const float*)d_in[3];
    const float* bk = (const float*)d_in[4];
    const float* Wv = (const float*)d_in[5];
    const float* bv = (const float*)d_in[6];
    float* out = (float*)d_out;

    cudaFuncSetAttribute(qkv_mma,
                         cudaFuncAttributeMaxDynamicSharedMemorySize, QK_SMEM);
    cudaFuncSetAttribute(attn_mma,
                         cudaFuncAttributeMaxDynamicSharedMemorySize, AT_SMEM);

    prep_pack<<<(NXT + NWT + 255) / 256, 256>>>(X, Wq, Wk, Wv);

    dim3 g1(D_ / 128, (B_ * S_) / 128, 3);   // (6, 64, 3)
    qkv_mma<<<g1, 256, QK_SMEM>>>(bq, bk, bv);

    dim3 g2(S_ / 128, H_, B_);               // (16, 12, 4)
    attn_mma<<<g2, 256, AT_SMEM>>>(out);
}